// round 13
// baseline (speedup 1.0000x reference)
#include <cuda_runtime.h>
#include <cstdint>

// Problem constants
#define B_TOTAL 1024
#define T_PRED  24
#define FEAT    15
#define FILT    64
#define LENC    168
#define NDIL    6

// Kernel config
#define BROWS   8     // batch rows per block
#define NBLK    (B_TOTAL / BROWS)   // 128
#define NT      512
#define KW      68    // padded row stride (floats) for transposed weights

static __device__ __forceinline__ float fast_tanh(float x) {
    float e;
    asm("ex2.approx.f32 %0, %1;" : "=f"(e) : "f"(x * 2.8853900817779268f)); // exp(2x)
    float r;
    asm("rcp.approx.f32 %0, %1;" : "=f"(r) : "f"(e + 1.0f));
    return fmaf(-2.0f, r, 1.0f);          // 1 - 2/(e^{2x}+1)
}
static __device__ __forceinline__ float fast_sigmoid(float x) {
    float e;
    asm("ex2.approx.f32 %0, %1;" : "=f"(e) : "f"(-x * 1.4426950408889634f)); // exp(-x)
    float r;
    asm("rcp.approx.f32 %0, %1;" : "=f"(r) : "f"(e + 1.0f));
    return r;                              // 1/(1+e^{-x})
}

static __device__ __forceinline__ void dot4(float& acc, const float4& v, const float4& u) {
    acc = fmaf(v.x, u.x, acc);
    acc = fmaf(v.y, u.y, acc);
    acc = fmaf(v.z, u.z, acc);
    acc = fmaf(v.w, u.w, acc);
}

// ---- shared memory layout (float offsets) ----
#define OFF_W2T  0
#define OFF_W3T  (128*KW)
#define OFF_W4T  (2*128*KW)
#define OFF_W1   (3*128*KW)            // 26112
#define OFF_W6   (OFF_W1 + 1024)
#define OFF_B1   (OFF_W6 + 128)
#define OFF_B2   (OFF_B1 + 64)
#define OFF_B4   (OFF_B2 + 128)
#define OFF_B5   (OFF_B4 + 128)
#define OFF_B6   (OFF_B5 + 128)
#define OFF_RING (OFF_B6 + 8)          // 31 slices * 512 floats (d=1,2,4,8,16 rings)
#define OFF_ENC5 (OFF_RING + 31*512)   // d=32 encoder stage
#define OFF_INP  (OFF_ENC5 + 512)      // inputs   [rg*64+j]
#define OFF_GAT  (OFF_INP + 512)       // gated    [rg*64+j]
#define OFF_CUR  (OFF_GAT + 512)       // cur      [rg*16+c]
#define OFF_SKP  (OFF_CUR + 128)       // skip     [rg*384 + i*64 + j] (relu'd)
#define OFF_WP   (OFF_SKP + 8*384)     // W5 partials [ks*1024 + r*128 + jc]
#define OFF_H    (OFF_WP + 4096)       // h        [r*128 + jc]
#define OFF_YP   (OFF_H + 1024)        // per-warp y partials [16]
#define OFF_PV   (OFF_YP + 16)         // prev y per row [8]
#define SMEM_FLOATS (OFF_PV + 8)       // = 53472 floats = 213888 B

__global__ __launch_bounds__(NT, 1)
void decoder_kernel(const float* __restrict__ feat,   // (1024, 24, 15)
                    const float* __restrict__ init,   // (1024, 1)
                    const float* __restrict__ enc,    // (6, 1024, 168, 64)
                    const float* __restrict__ gW1, const float* __restrict__ gb1,
                    const float* __restrict__ gW2, const float* __restrict__ gb2,
                    const float* __restrict__ gW3,
                    const float* __restrict__ gW4, const float* __restrict__ gb4,
                    const float* __restrict__ gW5, const float* __restrict__ gb5,
                    const float* __restrict__ gW6, const float* __restrict__ gb6,
                    float* __restrict__ out)          // (1024, 24)
{
    extern __shared__ float sm[];
    float* const ring = sm + OFF_RING;
    float* const enc5 = sm + OFF_ENC5;
    float* const inp  = sm + OFF_INP;
    float* const gat  = sm + OFF_GAT;
    float* const cur  = sm + OFF_CUR;
    float* const skp  = sm + OFF_SKP;
    float* const wp   = sm + OFF_WP;
    float* const hsm  = sm + OFF_H;
    float* const ypt  = sm + OFF_YP;
    float* const pv   = sm + OFF_PV;

    const int tid  = threadIdx.x;
    const int rg   = tid >> 6;        // row within block (0..7)
    const int j    = tid & 63;        // column half-index (0..63)
    const int row0 = blockIdx.x * BROWS;
    const int row  = row0 + rg;

    // ---- load + transpose weights into smem ----
    for (int idx = tid; idx < 8192; idx += NT) {
        int k = idx >> 7, c = idx & 127;              // W[k][c], (64,128) row-major
        sm[OFF_W2T + c*KW + k] = gW2[idx];
        sm[OFF_W3T + c*KW + k] = gW3[idx];
        sm[OFF_W4T + c*KW + k] = gW4[idx];
    }
    for (int idx = tid; idx < 1024; idx += NT) sm[OFF_W1 + idx] = gW1[idx];
    if (tid < 128) {
        sm[OFF_W6 + tid] = gW6[tid];
        sm[OFF_B2 + tid] = gb2[tid];
        sm[OFF_B4 + tid] = gb4[tid];
        sm[OFF_B5 + tid] = gb5[tid];
    }
    if (tid < 64) sm[OFF_B1 + tid] = gb1[tid];
    if (tid == 0) sm[OFF_B6] = gb6[0];
    if (tid < 8)  pv[tid] = init[row0 + tid];
    __syncthreads();

    // per-thread weight column pointers (transposed layout [col][k])
    const float* const w2a = sm + OFF_W2T + j*KW;
    const float* const w2b = sm + OFF_W2T + (j+64)*KW;
    const float* const w3a = sm + OFF_W3T + j*KW;
    const float* const w3b = sm + OFF_W3T + (j+64)*KW;
    const float* const w4a = sm + OFF_W4T + j*KW;
    const float* const w4b = sm + OFF_W4T + (j+64)*KW;
    const float bb2f = sm[OFF_B2 + j],  bb2g = sm[OFF_B2 + 64 + j];
    const float bb4s = sm[OFF_B4 + j],  bb4r = sm[OFF_B4 + 64 + j];
    const float bb1  = sm[OFF_B1 + j];

    for (int t = 0; t < T_PRED; t++) {
        // ---- Phase A: stage encoder slices (t<d -> into ring slot; d=32 always) + cur ----
        {
            const int k = j;
            #pragma unroll
            for (int i = 0; i < 5; i++) {
                const int d = 1 << i;
                if (t < d) {
                    float v = enc[(((size_t)i*B_TOTAL + row)*LENC + (LENC + t - d))*FILT + k];
                    ring[((d - 1) + (t & (d - 1)))*512 + rg*64 + k] = v;
                }
            }
            enc5[rg*64 + k] = enc[(((size_t)5*B_TOTAL + row)*LENC + (LENC + t - 32))*FILT + k];
            if (tid < 128) {
                int r = tid >> 4, c = tid & 15;
                cur[tid] = (c == 0) ? pv[r]
                                    : feat[(size_t)(row0 + r)*T_PRED*FEAT + t*FEAT + (c - 1)];
            }
        }
        __syncthreads();

        // ---- Phase B: inputs = tanh(cur @ W1 + b1) ----
        {
            float acc = bb1;
            #pragma unroll
            for (int k = 0; k < 16; k++)
                acc = fmaf(cur[rg*16 + k], sm[OFF_W1 + k*64 + j], acc);
            inp[rg*64 + j] = fast_tanh(acc);
        }
        __syncthreads();

        // ---- dilation stages (sequential) ----
        #pragma unroll 1
        for (int i = 0; i < NDIL; i++) {
            const int d = 1 << i;
            const float* st = (i < 5) ? (ring + ((d - 1) + (t & (d - 1)))*512 + rg*64)
                                      : (enc5 + rg*64);
            const float* in_r = inp + rg*64;

            // dilated[j], dilated[j+64] = state@W2 + b2 + inputs@W3
            float f = bb2f, g = bb2g;
            #pragma unroll
            for (int k = 0; k < 64; k += 4) {
                float4 s4 = *(const float4*)(st + k);
                float4 i4 = *(const float4*)(in_r + k);
                float4 wa = *(const float4*)(w2a + k);
                float4 wb = *(const float4*)(w2b + k);
                float4 wc = *(const float4*)(w3a + k);
                float4 wd = *(const float4*)(w3b + k);
                dot4(f, s4, wa);
                dot4(f, i4, wc);
                dot4(g, s4, wb);
                dot4(g, i4, wd);
            }
            gat[rg*64 + j] = fast_tanh(f) * fast_sigmoid(g);
            __syncthreads();

            // out = gated@W4 + b4 ; skips/residuals split
            float s = bb4s, res = bb4r;
            const float* g_r = gat + rg*64;
            #pragma unroll
            for (int k = 0; k < 64; k += 4) {
                float4 g4 = *(const float4*)(g_r + k);
                float4 wa = *(const float4*)(w4a + k);
                float4 wb = *(const float4*)(w4b + k);
                dot4(s,  g4, wa);
                dot4(res, g4, wb);
            }
            float ni = in_r[j] + res;                    // inputs += residuals
            skp[rg*384 + i*64 + j] = fmaxf(s, 0.0f);     // relu(skips) pre-applied
            if (i < 5) ring[((d - 1) + (t & (d - 1)))*512 + rg*64 + j] = ni; // appended[i][:,t,:]
            inp[rg*64 + j] = ni;
            __syncthreads();
        }

        // ---- Phase E: h_partial = skip @ W5 (4 k-segments x 128 cols) ----
        {
            const int jc = tid & 127;      // output column
            const int ks = tid >> 7;       // k-segment 0..3 (96 k each)
            const int kb = ks * 96;
            float acc[8] = {0,0,0,0,0,0,0,0};
            #pragma unroll 4
            for (int kq = 0; kq < 96; kq += 4) {
                const int k = kb + kq;
                float w0  = gW5[(k + 0)*128 + jc];
                float w1v = gW5[(k + 1)*128 + jc];
                float w2v = gW5[(k + 2)*128 + jc];
                float w3v = gW5[(k + 3)*128 + jc];
                #pragma unroll
                for (int r = 0; r < 8; r++) {
                    float4 s4 = *(const float4*)(skp + r*384 + k);
                    acc[r] = fmaf(s4.x, w0,
                             fmaf(s4.y, w1v,
                             fmaf(s4.z, w2v,
                             fmaf(s4.w, w3v, acc[r]))));
                }
            }
            #pragma unroll
            for (int r = 0; r < 8; r++)
                wp[ks*1024 + r*128 + jc] = acc[r];
        }
        __syncthreads();

        // ---- Phase F: reduce partials, + b5, relu -> h ----
        #pragma unroll
        for (int o = tid; o < 1024; o += NT) {
            float v = wp[o] + wp[1024 + o] + wp[2048 + o] + wp[3072 + o] + sm[OFF_B5 + (o & 127)];
            hsm[o] = fmaxf(v, 0.0f);
        }
        __syncthreads();

        // ---- Phase G: y = h @ W6 + b6 ----
        {
            float v = hsm[rg*128 + j]       * sm[OFF_W6 + j]
                    + hsm[rg*128 + 64 + j]  * sm[OFF_W6 + 64 + j];
            #pragma unroll
            for (int off = 16; off; off >>= 1)
                v += __shfl_down_sync(0xffffffffu, v, off);
            if ((tid & 31) == 0) ypt[tid >> 5] = v;
        }
        __syncthreads();
        if (tid < 8) {
            float y = ypt[2*tid] + ypt[2*tid + 1] + sm[OFF_B6];
            pv[tid] = y;
            out[(size_t)(row0 + tid)*T_PRED + t] = y;
        }
        __syncthreads();
    }
}

extern "C" void kernel_launch(void* const* d_in, const int* in_sizes, int n_in,
                              void* d_out, int out_size) {
    const float* feat = (const float*)d_in[0];   // decoder_features
    const float* init = (const float*)d_in[1];   // decoder_init_input
    const float* enc  = (const float*)d_in[2];   // encoder_states
    const float* W1 = (const float*)d_in[3];
    const float* b1 = (const float*)d_in[4];
    const float* W2 = (const float*)d_in[5];
    const float* b2 = (const float*)d_in[6];
    const float* W3 = (const float*)d_in[7];
    const float* W4 = (const float*)d_in[8];
    const float* b4 = (const float*)d_in[9];
    const float* W5 = (const float*)d_in[10];
    const float* b5 = (const float*)d_in[11];
    const float* W6 = (const float*)d_in[12];
    const float* b6 = (const float*)d_in[13];
    float* outp = (float*)d_out;

    const size_t smem_bytes = (size_t)SMEM_FLOATS * sizeof(float);
    cudaFuncSetAttribute(decoder_kernel,
                         cudaFuncAttributeMaxDynamicSharedMemorySize,
                         (int)smem_bytes);
    decoder_kernel<<<NBLK, NT, smem_bytes>>>(feat, init, enc,
                                             W1, b1, W2, b2, W3, W4, b4,
                                             W5, b5, W6, b6, outp);
}

// round 14
// speedup vs baseline: 1.4141x; 1.4141x over previous
#include <cuda_runtime.h>
#include <cstdint>

// Problem constants
#define B_TOTAL 1024
#define T_PRED  24
#define FEAT    15
#define FILT    64
#define LENC    168
#define NDIL    6

// Kernel config
#define BROWS   8     // batch rows per block
#define NBLK    (B_TOTAL / BROWS)   // 128
#define NT      512
#define KW      68    // padded row stride (floats) for transposed weights

static __device__ __forceinline__ float fast_tanh(float x) {
    float e;
    asm("ex2.approx.f32 %0, %1;" : "=f"(e) : "f"(x * 2.8853900817779268f)); // exp(2x)
    float r;
    asm("rcp.approx.f32 %0, %1;" : "=f"(r) : "f"(e + 1.0f));
    return fmaf(-2.0f, r, 1.0f);          // 1 - 2/(e^{2x}+1)
}
static __device__ __forceinline__ float fast_sigmoid(float x) {
    float e;
    asm("ex2.approx.f32 %0, %1;" : "=f"(e) : "f"(-x * 1.4426950408889634f)); // exp(-x)
    float r;
    asm("rcp.approx.f32 %0, %1;" : "=f"(r) : "f"(e + 1.0f));
    return r;                              // 1/(1+e^{-x})
}

static __device__ __forceinline__ void dot4(float& acc, const float4& v, const float4& u) {
    acc = fmaf(v.x, u.x, acc);
    acc = fmaf(v.y, u.y, acc);
    acc = fmaf(v.z, u.z, acc);
    acc = fmaf(v.w, u.w, acc);
}
// acc += s * w (componentwise)
static __device__ __forceinline__ void fma4s(float4& acc, float s, const float4& w) {
    acc.x = fmaf(s, w.x, acc.x);
    acc.y = fmaf(s, w.y, acc.y);
    acc.z = fmaf(s, w.z, acc.z);
    acc.w = fmaf(s, w.w, acc.w);
}

#define BAR256() asm volatile("bar.sync 1, 256;" ::: "memory")

// ---- shared memory layout (float offsets) ----
#define OFF_W2T  0
#define OFF_W3T  (128*KW)
#define OFF_W4T  (2*128*KW)
#define OFF_W1   (3*128*KW)            // 26112
#define OFF_W6   (OFF_W1 + 1024)
#define OFF_B1   (OFF_W6 + 128)
#define OFF_B2   (OFF_B1 + 64)
#define OFF_B4   (OFF_B2 + 128)
#define OFF_B5   (OFF_B4 + 128)
#define OFF_B6   (OFF_B5 + 128)
#define OFF_RING (OFF_B6 + 8)          // 31 slices * 512 floats (d=1,2,4,8,16 rings)
#define OFF_ENC5 (OFF_RING + 31*512)   // d=32 encoder stage
#define OFF_INP  (OFF_ENC5 + 512)      // inputs   [row*64+j]
#define OFF_GAT  (OFF_INP + 512)       // gated    [row*64+j]
#define OFF_CUR  (OFF_GAT + 512)       // cur      [row*16+c]
#define OFF_SKP  (OFF_CUR + 128)       // skip     [row*384 + i*64 + j] (relu'd)
#define OFF_WP   (OFF_SKP + 8*384)     // W5 partials [ks*1024 + r*128 + jc]
#define OFF_H    (OFF_WP + 4096)       // h        [r*128 + jc]
#define OFF_YP   (OFF_H + 1024)        // per-warp y partials [16]
#define OFF_PV   (OFF_YP + 16)         // prev y per row [8]
#define SMEM_FLOATS (OFF_PV + 8)       // = 53472 floats = 213888 B

__global__ __launch_bounds__(NT, 1)
void decoder_kernel(const float* __restrict__ feat,   // (1024, 24, 15)
                    const float* __restrict__ init,   // (1024, 1)
                    const float* __restrict__ enc,    // (6, 1024, 168, 64)
                    const float* __restrict__ gW1, const float* __restrict__ gb1,
                    const float* __restrict__ gW2, const float* __restrict__ gb2,
                    const float* __restrict__ gW3,
                    const float* __restrict__ gW4, const float* __restrict__ gb4,
                    const float* __restrict__ gW5, const float* __restrict__ gb5,
                    const float* __restrict__ gW6, const float* __restrict__ gb6,
                    float* __restrict__ out)          // (1024, 24)
{
    extern __shared__ float sm[];
    float* const ring = sm + OFF_RING;
    float* const enc5 = sm + OFF_ENC5;
    float* const inp  = sm + OFF_INP;
    float* const gat  = sm + OFF_GAT;
    float* const cur  = sm + OFF_CUR;
    float* const skp  = sm + OFF_SKP;
    float* const wp   = sm + OFF_WP;
    float* const hsm  = sm + OFF_H;
    float* const ypt  = sm + OFF_YP;
    float* const pv   = sm + OFF_PV;

    const int tid  = threadIdx.x;
    const int rg   = tid >> 6;        // row within block (0..7), for 512-wide phases
    const int j    = tid & 63;        // column within row, for 512-wide phases
    const int row0 = blockIdx.x * BROWS;
    const int row  = row0 + rg;

    // ---- load + transpose weights into smem ----
    for (int idx = tid; idx < 8192; idx += NT) {
        int k = idx >> 7, c = idx & 127;              // W[k][c], (64,128) row-major
        sm[OFF_W2T + c*KW + k] = gW2[idx];
        sm[OFF_W3T + c*KW + k] = gW3[idx];
        sm[OFF_W4T + c*KW + k] = gW4[idx];
    }
    for (int idx = tid; idx < 1024; idx += NT) sm[OFF_W1 + idx] = gW1[idx];
    if (tid < 128) {
        sm[OFF_W6 + tid] = gW6[tid];
        sm[OFF_B2 + tid] = gb2[tid];
        sm[OFF_B4 + tid] = gb4[tid];
        sm[OFF_B5 + tid] = gb5[tid];
    }
    if (tid < 64) sm[OFF_B1 + tid] = gb1[tid];
    if (tid == 0) sm[OFF_B6] = gb6[0];
    if (tid < 8)  pv[tid] = init[row0 + tid];
    __syncthreads();

    // Stage-phase thread mapping (first 256 threads): row-pair rp, column-pair (j2, j2+64)
    const int rp  = (tid >> 6) & 3;   // 0..3 (valid when tid < 256)
    const int j2  = tid & 63;
    const int r0s = 2 * rp;
    const int r1s = 2 * rp + 1;

    const float* const w2a = sm + OFF_W2T + j2*KW;
    const float* const w2b = sm + OFF_W2T + (j2+64)*KW;
    const float* const w3a = sm + OFF_W3T + j2*KW;
    const float* const w3b = sm + OFF_W3T + (j2+64)*KW;
    const float* const w4a = sm + OFF_W4T + j2*KW;
    const float* const w4b = sm + OFF_W4T + (j2+64)*KW;
    const float bb2f = sm[OFF_B2 + j2], bb2g = sm[OFF_B2 + 64 + j2];
    const float bb4s = sm[OFF_B4 + j2], bb4r = sm[OFF_B4 + 64 + j2];
    const float bb1  = sm[OFF_B1 + j];

    for (int t = 0; t < T_PRED; t++) {
        // ---- Phase A: stage encoder slices (t<d -> into ring slot; d=32 always) + cur ----
        {
            const int k = j;
            #pragma unroll
            for (int i = 0; i < 5; i++) {
                const int d = 1 << i;
                if (t < d) {
                    float v = enc[(((size_t)i*B_TOTAL + row)*LENC + (LENC + t - d))*FILT + k];
                    ring[((d - 1) + (t & (d - 1)))*512 + rg*64 + k] = v;
                }
            }
            enc5[rg*64 + k] = enc[(((size_t)5*B_TOTAL + row)*LENC + (LENC + t - 32))*FILT + k];
            if (tid < 128) {
                int r = tid >> 4, c = tid & 15;
                cur[tid] = (c == 0) ? pv[r]
                                    : feat[(size_t)(row0 + r)*T_PRED*FEAT + t*FEAT + (c - 1)];
            }
        }
        __syncthreads();

        // ---- Phase B: inputs = tanh(cur @ W1 + b1) ----
        {
            float acc = bb1;
            #pragma unroll
            for (int k = 0; k < 16; k++)
                acc = fmaf(cur[rg*16 + k], sm[OFF_W1 + k*64 + j], acc);
            inp[rg*64 + j] = fast_tanh(acc);
        }
        __syncthreads();

        // ---- dilation stages (sequential), 256 threads, R2C2 register blocking ----
        if (tid < 256) {
            #pragma unroll 1
            for (int i = 0; i < NDIL; i++) {
                const int d = 1 << i;
                const float* base = (i < 5) ? (ring + ((d - 1) + (t & (d - 1)))*512)
                                            : enc5;
                const float* st0 = base + r0s*64;
                const float* st1 = base + r1s*64;
                const float* in0 = inp + r0s*64;
                const float* in1 = inp + r1s*64;

                // dilated[j2], dilated[j2+64] for 2 rows = state@W2 + b2 + inputs@W3
                float f0 = bb2f, g0 = bb2g, f1 = bb2f, g1 = bb2g;
                #pragma unroll
                for (int k = 0; k < 64; k += 4) {
                    float4 wa = *(const float4*)(w2a + k);
                    float4 wb = *(const float4*)(w2b + k);
                    float4 wc = *(const float4*)(w3a + k);
                    float4 wd = *(const float4*)(w3b + k);
                    float4 s0 = *(const float4*)(st0 + k);
                    float4 i0 = *(const float4*)(in0 + k);
                    float4 s1 = *(const float4*)(st1 + k);
                    float4 i1 = *(const float4*)(in1 + k);
                    dot4(f0, s0, wa);  dot4(f0, i0, wc);
                    dot4(g0, s0, wb);  dot4(g0, i0, wd);
                    dot4(f1, s1, wa);  dot4(f1, i1, wc);
                    dot4(g1, s1, wb);  dot4(g1, i1, wd);
                }
                gat[r0s*64 + j2] = fast_tanh(f0) * fast_sigmoid(g0);
                gat[r1s*64 + j2] = fast_tanh(f1) * fast_sigmoid(g1);
                BAR256();

                // out = gated@W4 + b4 ; skips/residuals split
                float s0a = bb4s, res0 = bb4r, s1a = bb4s, res1 = bb4r;
                const float* g0r = gat + r0s*64;
                const float* g1r = gat + r1s*64;
                #pragma unroll
                for (int k = 0; k < 64; k += 4) {
                    float4 wa = *(const float4*)(w4a + k);
                    float4 wb = *(const float4*)(w4b + k);
                    float4 g0v = *(const float4*)(g0r + k);
                    float4 g1v = *(const float4*)(g1r + k);
                    dot4(s0a,  g0v, wa);
                    dot4(res0, g0v, wb);
                    dot4(s1a,  g1v, wa);
                    dot4(res1, g1v, wb);
                }
                float ni0 = inp[r0s*64 + j2] + res0;
                float ni1 = inp[r1s*64 + j2] + res1;
                skp[r0s*384 + i*64 + j2] = fmaxf(s0a, 0.0f);
                skp[r1s*384 + i*64 + j2] = fmaxf(s1a, 0.0f);
                if (i < 5) {
                    float* slot = ring + ((d - 1) + (t & (d - 1)))*512;
                    slot[r0s*64 + j2] = ni0;
                    slot[r1s*64 + j2] = ni1;
                }
                inp[r0s*64 + j2] = ni0;
                inp[r1s*64 + j2] = ni1;
                BAR256();
            }
        }
        __syncthreads();

        // ---- Phase E: h_partial = skip @ W5 (128 threads: 4 cols x 4 k-segments) ----
        if (tid < 128) {
            const int jc4 = (tid & 31) * 4;   // output columns [jc4, jc4+4)
            const int ks  = tid >> 5;         // k-segment 0..3 (96 k each)
            const int kb  = ks * 96;
            float4 acc[8];
            #pragma unroll
            for (int r = 0; r < 8; r++) acc[r] = make_float4(0.f, 0.f, 0.f, 0.f);
            #pragma unroll 4
            for (int kq = 0; kq < 96; kq += 4) {
                const int k = kb + kq;
                float4 w0 = *(const float4*)(gW5 + (size_t)(k + 0)*128 + jc4);
                float4 w1 = *(const float4*)(gW5 + (size_t)(k + 1)*128 + jc4);
                float4 w2 = *(const float4*)(gW5 + (size_t)(k + 2)*128 + jc4);
                float4 w3 = *(const float4*)(gW5 + (size_t)(k + 3)*128 + jc4);
                #pragma unroll
                for (int r = 0; r < 8; r++) {
                    float4 sv = *(const float4*)(skp + r*384 + k);
                    fma4s(acc[r], sv.x, w0);
                    fma4s(acc[r], sv.y, w1);
                    fma4s(acc[r], sv.z, w2);
                    fma4s(acc[r], sv.w, w3);
                }
            }
            #pragma unroll
            for (int r = 0; r < 8; r++)
                *(float4*)(wp + ks*1024 + r*128 + jc4) = acc[r];
        }
        __syncthreads();

        // ---- Phase F: reduce partials, + b5, relu -> h ----
        #pragma unroll
        for (int o = tid; o < 1024; o += NT) {
            float v = wp[o] + wp[1024 + o] + wp[2048 + o] + wp[3072 + o] + sm[OFF_B5 + (o & 127)];
            hsm[o] = fmaxf(v, 0.0f);
        }
        __syncthreads();

        // ---- Phase G: y = h @ W6 + b6 ----
        {
            float v = hsm[rg*128 + j]       * sm[OFF_W6 + j]
                    + hsm[rg*128 + 64 + j]  * sm[OFF_W6 + 64 + j];
            #pragma unroll
            for (int off = 16; off; off >>= 1)
                v += __shfl_down_sync(0xffffffffu, v, off);
            if ((tid & 31) == 0) ypt[tid >> 5] = v;
        }
        __syncthreads();
        if (tid < 8) {
            float y = ypt[2*tid] + ypt[2*tid + 1] + sm[OFF_B6];
            pv[tid] = y;
            out[(size_t)(row0 + tid)*T_PRED + t] = y;
        }
        __syncthreads();
    }
}

extern "C" void kernel_launch(void* const* d_in, const int* in_sizes, int n_in,
                              void* d_out, int out_size) {
    const float* feat = (const float*)d_in[0];   // decoder_features
    const float* init = (const float*)d_in[1];   // decoder_init_input
    const float* enc  = (const float*)d_in[2];   // encoder_states
    const float* W1 = (const float*)d_in[3];
    const float* b1 = (const float*)d_in[4];
    const float* W2 = (const float*)d_in[5];
    const float* b2 = (const float*)d_in[6];
    const float* W3 = (const float*)d_in[7];
    const float* W4 = (const float*)d_in[8];
    const float* b4 = (const float*)d_in[9];
    const float* W5 = (const float*)d_in[10];
    const float* b5 = (const float*)d_in[11];
    const float* W6 = (const float*)d_in[12];
    const float* b6 = (const float*)d_in[13];
    float* outp = (float*)d_out;

    const size_t smem_bytes = (size_t)SMEM_FLOATS * sizeof(float);
    cudaFuncSetAttribute(decoder_kernel,
                         cudaFuncAttributeMaxDynamicSharedMemorySize,
                         (int)smem_bytes);
    decoder_kernel<<<NBLK, NT, smem_bytes>>>(feat, init, enc,
                                             W1, b1, W2, b2, W3, W4, b4,
                                             W5, b5, W6, b6, outp);
}